// round 13
// baseline (speedup 1.0000x reference)
#include <cuda_runtime.h>
#include <cuda_bf16.h>
#include <math.h>
#include <stdint.h>

#define TT 16
#define CC 256
#define HS 64
#define FFD 1024
#define NT 512
#define PADQ 260
#define S2C 516

typedef unsigned long long u64t;
typedef unsigned int u32t;
typedef unsigned short u16t;

// global scratch (__device__ arrays: allowed, no allocation)
static __device__ u32t g_h2[(size_t)131072 * 256];   // packed bf16 hi|lo of LN2 out
static __device__ u32t g_ff[(size_t)131072 * 1024];  // packed bf16 hi|lo of relu ff

extern __shared__ __align__(16) char dynsm[];

// ---- f32x2 helpers ----
__device__ __forceinline__ u64t splat2(float v){ u64t r; asm("mov.b64 %0, {%1, %1};":"=l"(r):"f"(v)); return r; }
__device__ __forceinline__ void fma2(u64t& d, u64t a, u64t b){ asm("fma.rn.f32x2 %0, %1, %2, %0;":"+l"(d):"l"(a),"l"(b)); }
__device__ __forceinline__ void unpack2(float& lo, float& hi, u64t v){ asm("mov.b64 {%0, %1}, %2;":"=f"(lo),"=f"(hi):"l"(v)); }

__device__ __forceinline__ u16t f2bf(float f){ return __bfloat16_as_ushort(__float2bfloat16(f)); }
__device__ __forceinline__ float bf2f(u16t u){ return __bfloat162float(__ushort_as_bfloat16(u)); }
__device__ __forceinline__ u32t packsplit(float f){
    u16t h = f2bf(f);
    u16t l = f2bf(f - bf2f(h));
    return ((u32t)h << 16) | (u32t)l;
}

// warp-level bf16 MMA m16n8k16 (baseline sm_80+ PTX, valid on sm_103 target)
__device__ __forceinline__ void mma16816(float* c, const u32t* a, const u32t* b){
    asm volatile("mma.sync.aligned.m16n8k16.row.col.f32.bf16.bf16.f32 "
        "{%0,%1,%2,%3}, {%4,%5,%6,%7}, {%8,%9}, {%0,%1,%2,%3};"
        : "+f"(c[0]), "+f"(c[1]), "+f"(c[2]), "+f"(c[3])
        : "r"(a[0]), "r"(a[1]), "r"(a[2]), "r"(a[3]), "r"(b[0]), "r"(b[1]));
}

// SMEM tiles (bf16, stride 66 elems per row): Ah, Al: 128x66 ; Bh, Bl: 128x66
#define TILE_E (128 * 66)
#define GEMM_SMEM (4 * TILE_E * 2)

// C = A(packed hi|lo, row-major MxK) @ B(fp32 row-major KxN), bf16x3, fp32 accum
__device__ __forceinline__ void gemm_bf16x3(
    const u32t* __restrict__ Asrc, int Ald, int m0,
    const float* __restrict__ Bsrc, int Bld, int n0,
    int nchunks, float c[2][4][4],
    int wm, int wn, int g, int t, int tid)
{
    u16t* Ah = (u16t*)dynsm;
    u16t* Al = Ah + TILE_E;
    u16t* Bh = Al + TILE_E;
    u16t* Bl = Bh + TILE_E;
    const u32t* Ah32 = (const u32t*)Ah; const u32t* Al32 = (const u32t*)Al;
    const u32t* Bh32 = (const u32t*)Bh; const u32t* Bl32 = (const u32t*)Bl;

    for (int ch = 0; ch < nchunks; ch++){
        __syncthreads();
        // stage A chunk: 128 rows x 64 k
        for (int idx = tid; idx < 128*64; idx += NT){
            const int k = idx & 63, r = idx >> 6;
            const u32t v = Asrc[(size_t)(m0 + r) * Ald + ch*64 + k];
            Ah[r*66 + k] = (u16t)(v >> 16);
            Al[r*66 + k] = (u16t)(v & 0xffffu);
        }
        // stage B chunk: 64 k x 128 n -> stored [n][k]
        for (int idx = tid; idx < 64*128; idx += NT){
            const int n = idx & 127, k = idx >> 7;
            const float w = Bsrc[(size_t)(ch*64 + k) * Bld + n0 + n];
            const u16t h = f2bf(w);
            Bh[n*66 + k] = h;
            Bl[n*66 + k] = f2bf(w - bf2f(h));
        }
        __syncthreads();
        #pragma unroll
        for (int ks = 0; ks < 4; ks++){
            u32t ah[2][4], al[2][4], bh[4][2], bl[4][2];
            #pragma unroll
            for (int mb = 0; mb < 2; mb++){
                const int base = (wm*32 + mb*16 + g)*33 + ks*8 + t;
                ah[mb][0] = Ah32[base];        ah[mb][1] = Ah32[base + 8*33];
                ah[mb][2] = Ah32[base + 4];    ah[mb][3] = Ah32[base + 8*33 + 4];
                al[mb][0] = Al32[base];        al[mb][1] = Al32[base + 8*33];
                al[mb][2] = Al32[base + 4];    al[mb][3] = Al32[base + 8*33 + 4];
            }
            #pragma unroll
            for (int nb = 0; nb < 4; nb++){
                const int base = (wn*32 + nb*8 + g)*33 + ks*8 + t;
                bh[nb][0] = Bh32[base];  bh[nb][1] = Bh32[base + 4];
                bl[nb][0] = Bl32[base];  bl[nb][1] = Bl32[base + 4];
            }
            #pragma unroll
            for (int mb = 0; mb < 2; mb++)
                #pragma unroll
                for (int nb = 0; nb < 4; nb++){
                    mma16816(c[mb][nb], ah[mb], bh[nb]);
                    mma16816(c[mb][nb], ah[mb], bl[nb]);
                    mma16816(c[mb][nb], al[mb], bh[nb]);
                }
        }
    }
}

// ============ K1: per-batch LN1+QKV+attn+Wo+residual ============
#define K1_SMEM ((4096 + 8*S2C + 3*TT*PADQ + 4096) * 4)

__global__ __launch_bounds__(NT, 1)
void k1_attn(const float* __restrict__ x,
             const float* __restrict__ Wq, const float* __restrict__ Wk,
             const float* __restrict__ Wv, const float* __restrict__ Wo,
             const float* __restrict__ bo,
             const float* __restrict__ g1, const float* __restrict__ be1,
             const float* __restrict__ g2, const float* __restrict__ be2,
             float* __restrict__ out)
{
    float* sm = (float*)dynsm;
    float* xb  = sm;
    float* hb2 = xb + TT*CC;
    float* qb  = hb2 + 8*S2C;
    float* kb  = qb + TT*PADQ;
    float* vb  = kb + TT*PADQ;
    float* pb  = vb + TT*PADQ;

    const int b = blockIdx.x, tid = threadIdx.x, warp = tid >> 5, lane = tid & 31;
    const float* xg = x + (size_t)b * TT * CC;
    {
        const float4* src = (const float4*)xg; float4* dst = (float4*)xb;
        for (int i = tid; i < TT*CC/4; i += NT) dst[i] = src[i];
    }
    __syncthreads();
    {   // LN1
        const int r = warp; float s = 0.f, s2 = 0.f;
        for (int c = lane; c < CC; c += 32) { float v = xb[r*CC+c]; s += v; s2 += v*v; }
        #pragma unroll
        for (int o = 16; o > 0; o >>= 1) { s += __shfl_xor_sync(~0u,s,o); s2 += __shfl_xor_sync(~0u,s2,o); }
        float mu = s*(1.f/CC), var = s2*(1.f/CC)-mu*mu, rstd = rsqrtf(var+1e-5f);
        for (int c = lane; c < CC; c += 32)
            hb2[(r>>1)*S2C + c*2 + (r&1)] = (xb[r*CC+c]-mu)*rstd*g1[c] + be1[c];
    }
    __syncthreads();
    if (tid < 384) {   // QKV
        const int rhalf = tid/192, g = tid%192, mat = g>>6, col = (g&63)*4;
        const float* W; float* dst;
        if (mat==0){W=Wq;dst=qb;} else if (mat==1){W=Wk;dst=kb;} else {W=Wv;dst=vb;}
        const int h = col>>6, d = col&63;
        const float* wp = W + (size_t)h*CC*HS + d;
        const int rp0 = rhalf*4;
        u64t acc[4][4] = {};
        #pragma unroll 2
        for (int c = 0; c < CC; c += 2){
            const float4 wA = *(const float4*)(wp + (size_t)(c  )*HS);
            const float4 wB = *(const float4*)(wp + (size_t)(c+1)*HS);
            const u64t sA0=splat2(wA.x),sA1=splat2(wA.y),sA2=splat2(wA.z),sA3=splat2(wA.w);
            const u64t sB0=splat2(wB.x),sB1=splat2(wB.y),sB2=splat2(wB.z),sB3=splat2(wB.w);
            #pragma unroll
            for (int rp = 0; rp < 4; rp++){
                const ulonglong2 p = *(const ulonglong2*)&hb2[(rp0+rp)*S2C + c*2];
                fma2(acc[0][rp],p.x,sA0); fma2(acc[1][rp],p.x,sA1);
                fma2(acc[2][rp],p.x,sA2); fma2(acc[3][rp],p.x,sA3);
                fma2(acc[0][rp],p.y,sB0); fma2(acc[1][rp],p.y,sB1);
                fma2(acc[2][rp],p.y,sB2); fma2(acc[3][rp],p.y,sB3);
            }
        }
        #pragma unroll
        for (int rp = 0; rp < 4; rp++){
            float4 lo4, hi4;
            unpack2(lo4.x,hi4.x,acc[0][rp]); unpack2(lo4.y,hi4.y,acc[1][rp]);
            unpack2(lo4.z,hi4.z,acc[2][rp]); unpack2(lo4.w,hi4.w,acc[3][rp]);
            const int r0 = 2*(rp0+rp);
            *(float4*)&dst[r0*PADQ+col] = lo4; *(float4*)&dst[(r0+1)*PADQ+col] = hi4;
        }
    }
    __syncthreads();
    #pragma unroll
    for (int i = 0; i < 4; i++){   // attention
        const int task = warp*4+i, h = task>>4, t = task&15;
        const float* qrow = qb + t*PADQ + h*HS;
        float sc = -INFINITY;
        if (lane < TT && lane <= t){
            const float* krow = kb + lane*PADQ + h*HS;
            float a = 0.f;
            #pragma unroll
            for (int c = 0; c < HS; c += 4){
                const float4 qv = *(const float4*)&qrow[c];
                const float4 kv = *(const float4*)&krow[c];
                a += qv.x*kv.x + qv.y*kv.y + qv.z*kv.z + qv.w*kv.w;
            }
            sc = a * 0.0625f;
        }
        float m = sc;
        #pragma unroll
        for (int o = 8; o > 0; o >>= 1) m = fmaxf(m, __shfl_xor_sync(~0u, m, o, 16));
        const float e = __expf(sc - m);
        float ssum = e;
        #pragma unroll
        for (int o = 8; o > 0; o >>= 1) ssum += __shfl_xor_sync(~0u, ssum, o, 16);
        const float wgt = e / ssum;
        float o0 = 0.f, o1 = 0.f;
        for (int s2 = 0; s2 <= t; s2++){
            const float ws = __shfl_sync(~0u, wgt, s2);
            o0 += ws * vb[s2*PADQ + h*HS + lane];
            o1 += ws * vb[s2*PADQ + h*HS + lane + 32];
        }
        hb2[(t>>1)*S2C + (h*HS+lane)*2 + (t&1)]    = o0;
        hb2[(t>>1)*S2C + (h*HS+lane+32)*2 + (t&1)] = o1;
    }
    __syncthreads();
    {   // Wo + residual (K-split)
        const int khalf = tid>>8, rhalf = (tid>>7)&1, col = (tid&127)*2;
        const int rp0 = rhalf*4, c0 = khalf*128;
        const float* wp = Wo + col;
        u64t acc[2][4] = {};
        #pragma unroll 2
        for (int c = c0; c < c0+128; c += 2){
            const float2 wA = *(const float2*)(wp + (size_t)(c  )*CC);
            const float2 wB = *(const float2*)(wp + (size_t)(c+1)*CC);
            const u64t sA0=splat2(wA.x),sA1=splat2(wA.y),sB0=splat2(wB.x),sB1=splat2(wB.y);
            #pragma unroll
            for (int rp = 0; rp < 4; rp++){
                const ulonglong2 p = *(const ulonglong2*)&hb2[(rp0+rp)*S2C + c*2];
                fma2(acc[0][rp],p.x,sA0); fma2(acc[1][rp],p.x,sA1);
                fma2(acc[0][rp],p.y,sB0); fma2(acc[1][rp],p.y,sB1);
            }
        }
        if (khalf == 1){
            #pragma unroll
            for (int rp = 0; rp < 4; rp++){
                float l0,h0,l1,h1; unpack2(l0,h0,acc[0][rp]); unpack2(l1,h1,acc[1][rp]);
                const int r0 = 2*(rp0+rp);
                *(float2*)&pb[r0*CC+col] = make_float2(l0,l1);
                *(float2*)&pb[(r0+1)*CC+col] = make_float2(h0,h1);
            }
        }
        __syncthreads();
        if (khalf == 0){
            const float b0v = bo[col], b1v = bo[col+1];
            #pragma unroll
            for (int rp = 0; rp < 4; rp++){
                float l0,h0,l1,h1; unpack2(l0,h0,acc[0][rp]); unpack2(l1,h1,acc[1][rp]);
                const int r0 = 2*(rp0+rp);
                xb[r0*CC+col]       += b0v + l0 + pb[r0*CC+col];
                xb[r0*CC+col+1]     += b1v + l1 + pb[r0*CC+col+1];
                xb[(r0+1)*CC+col]   += b0v + h0 + pb[(r0+1)*CC+col];
                xb[(r0+1)*CC+col+1] += b1v + h1 + pb[(r0+1)*CC+col+1];
            }
        }
    }
    __syncthreads();
    {   // x1 -> out;  LN2 -> packed g_h2
        const int r = warp;
        float* og = out + (size_t)b * TT * CC;
        for (int c = lane; c < CC; c += 32) og[r*CC+c] = xb[r*CC+c];
        float s = 0.f, s2 = 0.f;
        for (int c = lane; c < CC; c += 32) { float v = xb[r*CC+c]; s += v; s2 += v*v; }
        #pragma unroll
        for (int o = 16; o > 0; o >>= 1) { s += __shfl_xor_sync(~0u,s,o); s2 += __shfl_xor_sync(~0u,s2,o); }
        float mu = s*(1.f/CC), var = s2*(1.f/CC)-mu*mu, rstd = rsqrtf(var+1e-5f);
        u32t* hg = g_h2 + ((size_t)b*TT + r) * CC;
        for (int c = lane; c < CC; c += 32)
            hg[c] = packsplit((xb[r*CC+c]-mu)*rstd*g2[c] + be2[c]);
    }
}

// ============ K2: ff = relu(h2 @ W1 + b1) ============
__global__ __launch_bounds__(NT, 1)
void k2_mlp1(const float* __restrict__ W1, const float* __restrict__ b1)
{
    const int tid = threadIdx.x, wid = tid >> 5, lane = tid & 31;
    const int wm = wid >> 2, wn = wid & 3, g = lane >> 2, t = lane & 3;
    const int m0 = (blockIdx.x >> 3) * 128, n0 = (blockIdx.x & 7) * 128;
    float c[2][4][4] = {};
    gemm_bf16x3(g_h2, 256, m0, W1, FFD, n0, 4, c, wm, wn, g, t, tid);
    #pragma unroll
    for (int mb = 0; mb < 2; mb++)
        #pragma unroll
        for (int nb = 0; nb < 4; nb++){
            const int row = m0 + wm*32 + mb*16 + g;
            const int col = n0 + wn*32 + nb*8 + 2*t;
            const float bx = b1[col], by = b1[col+1];
            uint2 p0, p1;
            p0.x = packsplit(fmaxf(c[mb][nb][0] + bx, 0.f));
            p0.y = packsplit(fmaxf(c[mb][nb][1] + by, 0.f));
            p1.x = packsplit(fmaxf(c[mb][nb][2] + bx, 0.f));
            p1.y = packsplit(fmaxf(c[mb][nb][3] + by, 0.f));
            *(uint2*)&g_ff[(size_t)row * FFD + col]       = p0;
            *(uint2*)&g_ff[(size_t)(row+8) * FFD + col]   = p1;
        }
}

// ============ K3: out = x1 + ff @ W2 + b2 ============
__global__ __launch_bounds__(NT, 1)
void k3_mlp2(const float* __restrict__ W2, const float* __restrict__ b2,
             float* __restrict__ out)
{
    const int tid = threadIdx.x, wid = tid >> 5, lane = tid & 31;
    const int wm = wid >> 2, wn = wid & 3, g = lane >> 2, t = lane & 3;
    const int m0 = (blockIdx.x >> 1) * 128, n0 = (blockIdx.x & 1) * 128;
    float c[2][4][4] = {};
    gemm_bf16x3(g_ff, FFD, m0, W2, CC, n0, 16, c, wm, wn, g, t, tid);
    #pragma unroll
    for (int mb = 0; mb < 2; mb++)
        #pragma unroll
        for (int nb = 0; nb < 4; nb++){
            const int row = m0 + wm*32 + mb*16 + g;
            const int col = n0 + wn*32 + nb*8 + 2*t;
            const float bx = b2[col], by = b2[col+1];
            float* o0 = out + (size_t)row * CC + col;
            float* o1 = out + (size_t)(row+8) * CC + col;
            o0[0] += c[mb][nb][0] + bx;  o0[1] += c[mb][nb][1] + by;
            o1[0] += c[mb][nb][2] + bx;  o1[1] += c[mb][nb][3] + by;
        }
}

extern "C" void kernel_launch(void* const* d_in, const int* in_sizes, int n_in,
                              void* d_out, int out_size)
{
    const float* x   = (const float*)d_in[0];
    const float* Wq  = (const float*)d_in[1];
    const float* Wk  = (const float*)d_in[2];
    const float* Wv  = (const float*)d_in[3];
    const float* Wo  = (const float*)d_in[4];
    const float* bo  = (const float*)d_in[5];
    const float* W1  = (const float*)d_in[6];
    const float* b1  = (const float*)d_in[7];
    const float* W2  = (const float*)d_in[8];
    const float* b2  = (const float*)d_in[9];
    const float* g1  = (const float*)d_in[10];
    const float* be1 = (const float*)d_in[11];
    const float* g2  = (const float*)d_in[12];
    const float* be2 = (const float*)d_in[13];
    float* out = (float*)d_out;

    cudaFuncSetAttribute(k1_attn, cudaFuncAttributeMaxDynamicSharedMemorySize, K1_SMEM);
    cudaFuncSetAttribute(k2_mlp1, cudaFuncAttributeMaxDynamicSharedMemorySize, GEMM_SMEM);
    cudaFuncSetAttribute(k3_mlp2, cudaFuncAttributeMaxDynamicSharedMemorySize, GEMM_SMEM);

    k1_attn<<<8192, NT, K1_SMEM>>>(x, Wq, Wk, Wv, Wo, bo, g1, be1, g2, be2, out);
    k2_mlp1<<<8192, NT, GEMM_SMEM>>>(W1, b1);
    k3_mlp2<<<2048, NT, GEMM_SMEM>>>(W2, b2, out);
}

// round 15
// speedup vs baseline: 1.6307x; 1.6307x over previous
#include <cuda_runtime.h>
#include <cuda_bf16.h>
#include <math.h>
#include <stdint.h>

#define TT 16
#define CC 256
#define HS 64
#define FFD 1024
#define NT 512
#define PADQ 260
#define S2C 516

typedef unsigned long long u64t;
typedef unsigned int u32t;
typedef unsigned short u16t;

// ---- global scratch (__device__ arrays; no allocation) ----
static __device__ u16t g_h2h[(size_t)131072 * 256];
static __device__ u16t g_h2l[(size_t)131072 * 256];
static __device__ u16t g_ffh[(size_t)131072 * 1024];
static __device__ u16t g_ffl[(size_t)131072 * 1024];
static __device__ u16t g_w1h[1024 * 256], g_w1l[1024 * 256];   // W1^T [n][k]
static __device__ u16t g_w2h[256 * 1024], g_w2l[256 * 1024];   // W2^T [n][k]

extern __shared__ __align__(128) char dynsm[];

// ---- f32x2 helpers (K1) ----
__device__ __forceinline__ u64t splat2(float v){ u64t r; asm("mov.b64 %0, {%1, %1};":"=l"(r):"f"(v)); return r; }
__device__ __forceinline__ void fma2(u64t& d, u64t a, u64t b){ asm("fma.rn.f32x2 %0, %1, %2, %0;":"+l"(d):"l"(a),"l"(b)); }
__device__ __forceinline__ void unpack2(float& lo, float& hi, u64t v){ asm("mov.b64 {%0, %1}, %2;":"=f"(lo),"=f"(hi):"l"(v)); }

__device__ __forceinline__ u16t f2bf(float f){ return __bfloat16_as_ushort(__float2bfloat16(f)); }
__device__ __forceinline__ float bf2f(u16t u){ return __bfloat162float(__ushort_as_bfloat16(u)); }

// ---- tensor-path helpers (baseline PTX: sm_80 features, safe on compute_103) ----
__device__ __forceinline__ u32t smem_u32(const void* p){
    u32t a; asm("{ .reg .u64 t; cvta.to.shared.u64 t, %1; cvt.u32.u64 %0, t; }":"=r"(a):"l"(p)); return a;
}
__device__ __forceinline__ void mma16816(float* c, const u32t* a, const u32t* b){
    asm volatile("mma.sync.aligned.m16n8k16.row.col.f32.bf16.bf16.f32 "
        "{%0,%1,%2,%3}, {%4,%5,%6,%7}, {%8,%9}, {%0,%1,%2,%3};"
        : "+f"(c[0]), "+f"(c[1]), "+f"(c[2]), "+f"(c[3])
        : "r"(a[0]), "r"(a[1]), "r"(a[2]), "r"(a[3]), "r"(b[0]), "r"(b[1]));
}
__device__ __forceinline__ void ldsm4(u32t r[4], u32t addr){
    asm volatile("ldmatrix.sync.aligned.m8n8.x4.shared.b16 {%0,%1,%2,%3}, [%4];"
        : "=r"(r[0]), "=r"(r[1]), "=r"(r[2]), "=r"(r[3]) : "r"(addr));
}
#define CP_ASYNC16(dst, src) asm volatile("cp.async.cg.shared.global [%0], [%1], 16;" :: "r"(dst), "l"(src))
#define CP_COMMIT asm volatile("cp.async.commit_group;" ::: "memory")
#define CP_WAIT1 asm volatile("cp.async.wait_group 1;" ::: "memory")
#define CP_WAIT0 asm volatile("cp.async.wait_group 0;" ::: "memory")

// tiles: 4 x [128 rows][64 u16] with 16B-chunk XOR swizzle; 16384 B each; 2 stages
#define TILE_B 16384
#define STAGE_B 65536
#define GEMM_SMEM (2 * STAGE_B)

__device__ __forceinline__ void stage_chunk(
    u32t sb, int st, int ch,
    const u16t* __restrict__ Ah, const u16t* __restrict__ Al, int Ald, int m0,
    const u16t* __restrict__ Bh, const u16t* __restrict__ Bl, int Bld, int n0,
    int tid)
{
    const u32t base = sb + st * STAGE_B;
    for (int idx = tid; idx < 4096; idx += NT){
        const int tile = idx >> 10, r = (idx >> 3) & 127, c8 = idx & 7;
        const u32t dst = base + tile * TILE_B + ((r << 6) + ((c8 ^ (r & 7)) << 3)) * 2;
        const u16t* src;
        if      (tile == 0) src = Ah + (size_t)(m0 + r) * Ald + ch * 64 + c8 * 8;
        else if (tile == 1) src = Al + (size_t)(m0 + r) * Ald + ch * 64 + c8 * 8;
        else if (tile == 2) src = Bh + (size_t)(n0 + r) * Bld + ch * 64 + c8 * 8;
        else                src = Bl + (size_t)(n0 + r) * Bld + ch * 64 + c8 * 8;
        CP_ASYNC16(dst, src);
    }
    CP_COMMIT;
}

// C[128x128] = A(hi+lo) @ B(hi+lo)^T, 3-pass bf16, fp32 accum.
__device__ __forceinline__ void gemm_core(
    const u16t* __restrict__ Ah, const u16t* __restrict__ Al, int Ald, int m0,
    const u16t* __restrict__ Bh, const u16t* __restrict__ Bl, int Bld, int n0,
    int nch, float c[2][4][4])
{
    const int tid = threadIdx.x, wid = tid >> 5, lane = tid & 31;
    const int wm = wid >> 2, wn = wid & 3;
    const u32t sb = smem_u32(dynsm);

    stage_chunk(sb, 0, 0, Ah, Al, Ald, m0, Bh, Bl, Bld, n0, tid);

    for (int ch = 0; ch < nch; ch++){
        if (ch + 1 < nch){
            stage_chunk(sb, (ch + 1) & 1, ch + 1, Ah, Al, Ald, m0, Bh, Bl, Bld, n0, tid);
            CP_WAIT1;
        } else {
            CP_WAIT0;
        }
        __syncthreads();
        const u32t base = sb + (ch & 1) * STAGE_B;
        #pragma unroll
        for (int ks = 0; ks < 4; ks++){
            u32t ah[2][4], al[2][4];
            #pragma unroll
            for (int mb = 0; mb < 2; mb++){
                const int row = wm * 32 + mb * 16 + (lane & 15);
                const int kc  = (ks * 16 + (lane >> 4) * 8) >> 3;
                const u32t off = ((row << 6) + ((kc ^ (row & 7)) << 3)) * 2;
                ldsm4(ah[mb], base + off);
                ldsm4(al[mb], base + TILE_B + off);
            }
            u32t bh[2][4], bl[2][4];
            #pragma unroll
            for (int p = 0; p < 2; p++){
                const int row = wn * 32 + p * 16 + ((lane >> 3) & 1) * 8 + (lane & 7);
                const int kc  = (ks * 16 + (lane >> 4) * 8) >> 3;
                const u32t off = ((row << 6) + ((kc ^ (row & 7)) << 3)) * 2;
                ldsm4(bh[p], base + 2 * TILE_B + off);
                ldsm4(bl[p], base + 3 * TILE_B + off);
            }
            #pragma unroll
            for (int mb = 0; mb < 2; mb++){
                #pragma unroll
                for (int p = 0; p < 2; p++){
                    u32t be0[2] = {bh[p][0], bh[p][2]}, be1[2] = {bh[p][1], bh[p][3]};
                    u32t bo0[2] = {bl[p][0], bl[p][2]}, bo1[2] = {bl[p][1], bl[p][3]};
                    mma16816(c[mb][p*2],   ah[mb], be0);
                    mma16816(c[mb][p*2],   ah[mb], bo0);
                    mma16816(c[mb][p*2],   al[mb], be0);
                    mma16816(c[mb][p*2+1], ah[mb], be1);
                    mma16816(c[mb][p*2+1], ah[mb], bo1);
                    mma16816(c[mb][p*2+1], al[mb], be1);
                }
            }
        }
        __syncthreads();
    }
}

// ============ K0: one-time weight transpose + bf16 hi/lo split ============
__global__ __launch_bounds__(512)
void k0_conv(const float* __restrict__ W1, const float* __restrict__ W2)
{
    const int idx = blockIdx.x * 512 + threadIdx.x;
    if (idx < 262144){
        const int n = idx >> 8, k = idx & 255;
        const float w = W1[(size_t)k * FFD + n];
        const u16t h = f2bf(w);
        g_w1h[n * 256 + k] = h;
        g_w1l[n * 256 + k] = f2bf(w - bf2f(h));
    } else {
        const int j = idx - 262144;
        const int n = j >> 10, k = j & 1023;
        const float w = W2[(size_t)k * CC + n];
        const u16t h = f2bf(w);
        g_w2h[n * 1024 + k] = h;
        g_w2l[n * 1024 + k] = f2bf(w - bf2f(h));
    }
}

// ============ K1: per-batch LN1+QKV+attn+Wo+residual (f32x2) ============
#define K1_SMEM ((4096 + 8*S2C + 3*TT*PADQ + 4096) * 4)

__global__ __launch_bounds__(NT, 1)
void k1_attn(const float* __restrict__ x,
             const float* __restrict__ Wq, const float* __restrict__ Wk,
             const float* __restrict__ Wv, const float* __restrict__ Wo,
             const float* __restrict__ bo,
             const float* __restrict__ g1, const float* __restrict__ be1,
             const float* __restrict__ g2, const float* __restrict__ be2,
             float* __restrict__ out)
{
    float* sm = (float*)dynsm;
    float* xb  = sm;
    float* hb2 = xb + TT*CC;
    float* qb  = hb2 + 8*S2C;
    float* kb  = qb + TT*PADQ;
    float* vb  = kb + TT*PADQ;
    float* pb  = vb + TT*PADQ;

    const int b = blockIdx.x, tid = threadIdx.x, warp = tid >> 5, lane = tid & 31;
    const float* xg = x + (size_t)b * TT * CC;
    {
        const float4* src = (const float4*)xg; float4* dst = (float4*)xb;
        for (int i = tid; i < TT*CC/4; i += NT) dst[i] = src[i];
    }
    __syncthreads();
    {   // LN1
        const int r = warp; float s = 0.f, s2 = 0.f;
        for (int c = lane; c < CC; c += 32) { float v = xb[r*CC+c]; s += v; s2 += v*v; }
        #pragma unroll
        for (int o = 16; o > 0; o >>= 1) { s += __shfl_xor_sync(~0u,s,o); s2 += __shfl_xor_sync(~0u,s2,o); }
        float mu = s*(1.f/CC), var = s2*(1.f/CC)-mu*mu, rstd = rsqrtf(var+1e-5f);
        for (int c = lane; c < CC; c += 32)
            hb2[(r>>1)*S2C + c*2 + (r&1)] = (xb[r*CC+c]-mu)*rstd*g1[c] + be1[c];
    }
    __syncthreads();
    if (tid < 384) {   // QKV
        const int rhalf = tid/192, g = tid%192, mat = g>>6, col = (g&63)*4;
        const float* W; float* dst;
        if (mat==0){W=Wq;dst=qb;} else if (mat==1){W=Wk;dst=kb;} else {W=Wv;dst=vb;}
        const int h = col>>6, d = col&63;
        const float* wp = W + (size_t)h*CC*HS + d;
        const int rp0 = rhalf*4;
        u64t acc[4][4] = {};
        #pragma unroll 2
        for (int c = 0; c < CC; c += 2){
            const float4 wA = *(const float4*)(wp + (size_t)(c  )*HS);
            const float4 wB = *(const float4*)(wp + (size_t)(c+1)*HS);
            const u64t sA0=splat2(wA.x),sA1=splat2(wA.y),sA2=splat2(wA.z),sA3=splat2(wA.w);
            const u64t sB0=splat2(wB.x),sB1=splat2(wB.y),sB2=splat2(wB.z),sB3=splat2(wB.w);
            #pragma unroll
            for (int rp = 0; rp < 4; rp++){
                const ulonglong2 p = *(const ulonglong2*)&hb2[(rp0+rp)*S2C + c*2];
                fma2(acc[0][rp],p.x,sA0); fma2(acc[1][rp],p.x,sA1);
                fma2(acc[2][rp],p.x,sA2); fma2(acc[3][rp],p.x,sA3);
                fma2(acc[0][rp],p.y,sB0); fma2(acc[1][rp],p.y,sB1);
                fma2(acc[2][rp],p.y,sB2); fma2(acc[3][rp],p.y,sB3);
            }
        }
        #pragma unroll
        for (int rp = 0; rp < 4; rp++){
            float4 lo4, hi4;
            unpack2(lo4.x,hi4.x,acc[0][rp]); unpack2(lo4.y,hi4.y,acc[1][rp]);
            unpack2(lo4.z,hi4.z,acc[2][rp]); unpack2(lo4.w,hi4.w,acc[3][rp]);
            const int r0 = 2*(rp0+rp);
            *(float4*)&dst[r0*PADQ+col] = lo4; *(float4*)&dst[(r0+1)*PADQ+col] = hi4;
        }
    }
    __syncthreads();
    #pragma unroll
    for (int i = 0; i < 4; i++){   // attention
        const int task = warp*4+i, h = task>>4, t = task&15;
        const float* qrow = qb + t*PADQ + h*HS;
        float sc = -INFINITY;
        if (lane < TT && lane <= t){
            const float* krow = kb + lane*PADQ + h*HS;
            float a = 0.f;
            #pragma unroll
            for (int c = 0; c < HS; c += 4){
                const float4 qv = *(const float4*)&qrow[c];
                const float4 kv = *(const float4*)&krow[c];
                a += qv.x*kv.x + qv.y*kv.y + qv.z*kv.z + qv.w*kv.w;
            }
            sc = a * 0.0625f;
        }
        float m = sc;
        #pragma unroll
        for (int o = 8; o > 0; o >>= 1) m = fmaxf(m, __shfl_xor_sync(~0u, m, o, 16));
        const float e = __expf(sc - m);
        float ssum = e;
        #pragma unroll
        for (int o = 8; o > 0; o >>= 1) ssum += __shfl_xor_sync(~0u, ssum, o, 16);
        const float wgt = e / ssum;
        float o0 = 0.f, o1 = 0.f;
        for (int s2 = 0; s2 <= t; s2++){
            const float ws = __shfl_sync(~0u, wgt, s2);
            o0 += ws * vb[s2*PADQ + h*HS + lane];
            o1 += ws * vb[s2*PADQ + h*HS + lane + 32];
        }
        hb2[(t>>1)*S2C + (h*HS+lane)*2 + (t&1)]    = o0;
        hb2[(t>>1)*S2C + (h*HS+lane+32)*2 + (t&1)] = o1;
    }
    __syncthreads();
    {   // Wo + residual (K-split)
        const int khalf = tid>>8, rhalf = (tid>>7)&1, col = (tid&127)*2;
        const int rp0 = rhalf*4, c0 = khalf*128;
        const float* wp = Wo + col;
        u64t acc[2][4] = {};
        #pragma unroll 2
        for (int c = c0; c < c0+128; c += 2){
            const float2 wA = *(const float2*)(wp + (size_t)(c  )*CC);
            const float2 wB = *(const float2*)(wp + (size_t)(c+1)*CC);
            const u64t sA0=splat2(wA.x),sA1=splat2(wA.y),sB0=splat2(wB.x),sB1=splat2(wB.y);
            #pragma unroll
            for (int rp = 0; rp < 4; rp++){
                const ulonglong2 p = *(const ulonglong2*)&hb2[(rp0+rp)*S2C + c*2];
                fma2(acc[0][rp],p.x,sA0); fma2(acc[1][rp],p.x,sA1);
                fma2(acc[0][rp],p.y,sB0); fma2(acc[1][rp],p.y,sB1);
            }
        }
        if (khalf == 1){
            #pragma unroll
            for (int rp = 0; rp < 4; rp++){
                float l0,h0,l1,h1; unpack2(l0,h0,acc[0][rp]); unpack2(l1,h1,acc[1][rp]);
                const int r0 = 2*(rp0+rp);
                *(float2*)&pb[r0*CC+col] = make_float2(l0,l1);
                *(float2*)&pb[(r0+1)*CC+col] = make_float2(h0,h1);
            }
        }
        __syncthreads();
        if (khalf == 0){
            const float b0v = bo[col], b1v = bo[col+1];
            #pragma unroll
            for (int rp = 0; rp < 4; rp++){
                float l0,h0,l1,h1; unpack2(l0,h0,acc[0][rp]); unpack2(l1,h1,acc[1][rp]);
                const int r0 = 2*(rp0+rp);
                xb[r0*CC+col]       += b0v + l0 + pb[r0*CC+col];
                xb[r0*CC+col+1]     += b1v + l1 + pb[r0*CC+col+1];
                xb[(r0+1)*CC+col]   += b0v + h0 + pb[(r0+1)*CC+col];
                xb[(r0+1)*CC+col+1] += b1v + h1 + pb[(r0+1)*CC+col+1];
            }
        }
    }
    __syncthreads();
    {   // x1 -> out;  LN2 -> bf16 hi/lo scratch
        const int r = warp;
        float* og = out + (size_t)b * TT * CC;
        for (int c = lane; c < CC; c += 32) og[r*CC+c] = xb[r*CC+c];
        float s = 0.f, s2 = 0.f;
        for (int c = lane; c < CC; c += 32) { float v = xb[r*CC+c]; s += v; s2 += v*v; }
        #pragma unroll
        for (int o = 16; o > 0; o >>= 1) { s += __shfl_xor_sync(~0u,s,o); s2 += __shfl_xor_sync(~0u,s2,o); }
        float mu = s*(1.f/CC), var = s2*(1.f/CC)-mu*mu, rstd = rsqrtf(var+1e-5f);
        u16t* hh = g_h2h + ((size_t)b*TT + r) * CC;
        u16t* hl = g_h2l + ((size_t)b*TT + r) * CC;
        for (int c = lane; c < CC; c += 32){
            const float v = (xb[r*CC+c]-mu)*rstd*g2[c] + be2[c];
            const u16t h = f2bf(v);
            hh[c] = h; hl[c] = f2bf(v - bf2f(h));
        }
    }
}

// ============ K2: ff = relu(h2 @ W1 + b1) ============
__global__ __launch_bounds__(NT, 1)
void k2_mlp1(const float* __restrict__ b1)
{
    const int tid = threadIdx.x, wid = tid >> 5, lane = tid & 31;
    const int wm = wid >> 2, wn = wid & 3, g = lane >> 2, t = lane & 3;
    const int m0 = (blockIdx.x >> 3) * 128, n0 = (blockIdx.x & 7) * 128;
    float c[2][4][4] = {};
    gemm_core(g_h2h, g_h2l, 256, m0, g_w1h, g_w1l, 256, n0, 4, c);
    #pragma unroll
    for (int mb = 0; mb < 2; mb++)
        #pragma unroll
        for (int nb = 0; nb < 4; nb++){
            const int row = m0 + wm*32 + mb*16 + g;
            const int col = n0 + wn*32 + (nb>>1)*16 + (nb&1)*8 + 2*t;
            const float bx = b1[col], by = b1[col+1];
            #pragma unroll
            for (int hh = 0; hh < 2; hh++){
                const float v0 = fmaxf(c[mb][nb][hh*2]   + bx, 0.f);
                const float v1 = fmaxf(c[mb][nb][hh*2+1] + by, 0.f);
                const u16t h0 = f2bf(v0), h1 = f2bf(v1);
                const u16t l0 = f2bf(v0 - bf2f(h0)), l1 = f2bf(v1 - bf2f(h1));
                const size_t o = ((size_t)(row + hh*8)) * FFD + col;
                *(u32t*)&g_ffh[o] = (u32t)h0 | ((u32t)h1 << 16);
                *(u32t*)&g_ffl[o] = (u32t)l0 | ((u32t)l1 << 16);
            }
        }
}

// ============ K3: out = x1 + ff @ W2 + b2 ============
__global__ __launch_bounds__(NT, 1)
void k3_mlp2(const float* __restrict__ b2, float* __restrict__ out)
{
    const int tid = threadIdx.x, wid = tid >> 5, lane = tid & 31;
    const int wm = wid >> 2, wn = wid & 3, g = lane >> 2, t = lane & 3;
    const int m0 = (blockIdx.x >> 1) * 128, n0 = (blockIdx.x & 1) * 128;
    float c[2][4][4] = {};
    gemm_core(g_ffh, g_ffl, 1024, m0, g_w2h, g_w2l, 1024, n0, 16, c);
    #pragma unroll
    for (int mb = 0; mb < 2; mb++)
        #pragma unroll
        for (int nb = 0; nb < 4; nb++){
            const int row = m0 + wm*32 + mb*16 + g;
            const int col = n0 + wn*32 + (nb>>1)*16 + (nb&1)*8 + 2*t;
            const float bx = b2[col], by = b2[col+1];
            #pragma unroll
            for (int hh = 0; hh < 2; hh++){
                float2* o = (float2*)&out[((size_t)(row + hh*8)) * CC + col];
                float2 v = *o;
                v.x += c[mb][nb][hh*2]   + bx;
                v.y += c[mb][nb][hh*2+1] + by;
                *o = v;
            }
        }
}

extern "C" void kernel_launch(void* const* d_in, const int* in_sizes, int n_in,
                              void* d_out, int out_size)
{
    const float* x   = (const float*)d_in[0];
    const float* Wq  = (const float*)d_in[1];
    const float* Wk  = (const float*)d_in[2];
    const float* Wv  = (const float*)d_in[3];
    const float* Wo  = (const float*)d_in[4];
    const float* bo  = (const float*)d_in[5];
    const float* W1  = (const float*)d_in[6];
    const float* b1  = (const float*)d_in[7];
    const float* W2  = (const float*)d_in[8];
    const float* b2  = (const float*)d_in[9];
    const float* g1  = (const float*)d_in[10];
    const float* be1 = (const float*)d_in[11];
    const float* g2  = (const float*)d_in[12];
    const float* be2 = (const float*)d_in[13];
    float* out = (float*)d_out;

    cudaFuncSetAttribute(k1_attn, cudaFuncAttributeMaxDynamicSharedMemorySize, K1_SMEM);
    cudaFuncSetAttribute(k2_mlp1, cudaFuncAttributeMaxDynamicSharedMemorySize, GEMM_SMEM);
    cudaFuncSetAttribute(k3_mlp2, cudaFuncAttributeMaxDynamicSharedMemorySize, GEMM_SMEM);

    k0_conv<<<1024, 512>>>(W1, W2);
    k1_attn<<<8192, NT, K1_SMEM>>>(x, Wq, Wk, Wv, Wo, bo, g1, be1, g2, be2, out);
    k2_mlp1<<<8192, NT, GEMM_SMEM>>>(b1);
    k3_mlp2<<<2048, NT, GEMM_SMEM>>>(b2, out);
}